// round 14
// baseline (speedup 1.0000x reference)
#include <cuda_runtime.h>
#include <cuda_fp16.h>
#include <math_constants.h>
#include <cstdint>

#define D_MODEL 1024
#define SEQ     2048
#define BATCH   2
#define HEADS   16
#define KD      64
#define MROWS   (BATCH*SEQ)   // 4096

// ---- scratch (device globals) ----
__device__ __half g_Wh[6][D_MODEL*D_MODEL];    // fp16 Wq,Wk,Wv,Wqm,Wkm,Wvm
__device__ __half g_xh[MROWS*D_MODEL];
__device__ __half g_yh[MROWS*D_MODEL];
__device__ __half g_Weffh[3][D_MODEL*D_MODEL]; // fp16 fused weights (z=0 *QSC)
__device__ float  g_beff[3][D_MODEL];
__device__ __half g_QKVh[3][MROWS*D_MODEL];    // fp16 Q(,*QSC)/K/V

#define QSC 0.18033688011112042f               // 0.125 * log2(e)

// =====================================================================
// helpers
// =====================================================================
__device__ __forceinline__ float ex2f(float x) {
    float r;
    asm("ex2.approx.ftz.f32 %0, %1;" : "=f"(r) : "f"(x));
    return r;
}
__device__ __forceinline__ uint32_t smem_u32(const void* p) {
    uint32_t a;
    asm("{ .reg .u64 t; cvta.to.shared.u64 t, %1; cvt.u32.u64 %0, t; }" : "=r"(a) : "l"(p));
    return a;
}
__device__ __forceinline__ uint32_t packh2(float hi, float lo) {
    uint32_t r;
    asm("cvt.rn.f16x2.f32 %0, %1, %2;" : "=r"(r) : "f"(hi), "f"(lo));
    return r;
}
__device__ __forceinline__ void mma16(float* d, const uint32_t* a, const uint32_t* b) {
    asm volatile(
        "mma.sync.aligned.m16n8k16.row.col.f32.f16.f16.f32 "
        "{%0,%1,%2,%3}, {%4,%5,%6,%7}, {%8,%9}, {%0,%1,%2,%3};"
        : "+f"(d[0]), "+f"(d[1]), "+f"(d[2]), "+f"(d[3])
        : "r"(a[0]), "r"(a[1]), "r"(a[2]), "r"(a[3]), "r"(b[0]), "r"(b[1]));
}
__device__ __forceinline__ void ldsm4(uint32_t* r, uint32_t baddr) {
    asm volatile("ldmatrix.sync.aligned.m8n8.x4.shared.b16 {%0,%1,%2,%3}, [%4];"
        : "=r"(r[0]), "=r"(r[1]), "=r"(r[2]), "=r"(r[3]) : "r"(baddr));
}
__device__ __forceinline__ void ldsm4t(uint32_t* r, uint32_t baddr) {
    asm volatile("ldmatrix.sync.aligned.m8n8.x4.trans.shared.b16 {%0,%1,%2,%3}, [%4];"
        : "=r"(r[0]), "=r"(r[1]), "=r"(r[2]), "=r"(r[3]) : "r"(baddr));
}
#define CP16(smaddr, gptr) \
    asm volatile("cp.async.cg.shared.global [%0], [%1], 16;" :: "r"(smaddr), "l"(gptr) : "memory")
#define CP_COMMIT() asm volatile("cp.async.commit_group;" ::: "memory")
#define CP_WAIT0()  asm volatile("cp.async.wait_group 0;" ::: "memory")
#define CP_WAIT1()  asm volatile("cp.async.wait_group 1;" ::: "memory")

// =====================================================================
// pre-round pass: f32 -> fp16 (RNE) for x, y, 6 weights
// =====================================================================
__global__ void preround(const float* __restrict__ x, const float* __restrict__ y,
                         const float* __restrict__ Wq, const float* __restrict__ Wk,
                         const float* __restrict__ Wv, const float* __restrict__ Wqm,
                         const float* __restrict__ Wkm, const float* __restrict__ Wvm)
{
    int z = blockIdx.y;
    const float* src;
    __half* dst;
    int nf4;
    if (z == 0)      { src = x; dst = g_xh; nf4 = MROWS * D_MODEL / 4; }
    else if (z == 1) { src = y; dst = g_yh; nf4 = MROWS * D_MODEL / 4; }
    else {
        const float* ws[6] = { Wq, Wk, Wv, Wqm, Wkm, Wvm };
        src = ws[z - 2]; dst = g_Wh[z - 2]; nf4 = D_MODEL * D_MODEL / 4;
    }
    int i = blockIdx.x * 256 + threadIdx.x;
    if (i >= nf4) return;
    float4 v = ((const float4*)src)[i];
    __half2* d2 = (__half2*)dst;
    d2[2 * i]     = __floats2half2_rn(v.x, v.y);
    d2[2 * i + 1] = __floats2half2_rn(v.z, v.w);
}

// =====================================================================
// fp16 mma.sync GEMM: 128x128 CTA tile, 8 warps (2x4 -> 64x32 warp tile),
// K chunks of 64 (16 stages), 3-stage cp.async ring, ldmatrix fragments.
// LDA=72 / LDB=136 (halfs): ldmatrix rows conflict-free.
// =====================================================================
#define KC      64
#define NSTG    (D_MODEL / KC)     // 16
#define NBUF    3
#define LDA     72
#define LDB     136
#define ASZ     (128 * LDA)        // 9216 halfs
#define BSZ     (KC * LDB)         // 8704 halfs
#define STGSZ   (ASZ + BSZ)        // 17920 halfs
#define GEMM_SMEM (NBUF * STGSZ * 2)   // 107520 B

template<bool BIAS>
__device__ void gemm_cp(const __half* __restrict__ A, const __half* __restrict__ B,
                        const float* __restrict__ bias, __half* __restrict__ C,
                        float oscale)
{
    extern __shared__ __half smh[];
    const uint32_t us = smem_u32(smh);

    const int tid = threadIdx.x;
    const int wid = tid >> 5, lane = tid & 31;
    const int g = lane >> 2, c = lane & 3;
    const int wm = (wid & 1) * 64, wn = (wid >> 1) * 32;
    const int bm = blockIdx.y * 128, bn = blockIdx.x * 128;

    auto issue_stage = [&](int kc, int buf) {
        // A: 128 rows x 128B (8 chunks/row); 256 threads x 4 chunks
        int arow = tid >> 1;
        uint32_t da = us + (uint32_t)(buf * STGSZ + arow * LDA) * 2 + (tid & 1) * 64;
        const __half* ga = A + (size_t)(bm + arow) * D_MODEL + kc + (tid & 1) * 32;
#pragma unroll
        for (int q = 0; q < 4; q++) CP16(da + q * 16, ga + q * 8);
        // B: 64 rows x 256B (16 chunks/row); 256 threads x 4 chunks
        int brow = tid >> 2;
        uint32_t db = us + (uint32_t)(buf * STGSZ + ASZ + brow * LDB) * 2 + (tid & 3) * 64;
        const __half* gb = B + (size_t)(kc + brow) * D_MODEL + bn + (tid & 3) * 32;
#pragma unroll
        for (int q = 0; q < 4; q++) CP16(db + q * 16, gb + q * 8);
        CP_COMMIT();
    };

    issue_stage(0, 0);
    issue_stage(KC, 1);

    float acc[4][4][4] = {};

    const int lrA = ((lane >> 3) & 1) * 8 + (lane & 7);
    const int lcA = ((lane >> 4) & 1) * 8;
    const int lrB = ((lane >> 3) & 1) * 8 + (lane & 7);
    const int lcB = ((lane >> 4) & 1) * 8;

    for (int s = 0; s < NSTG; s++) {
        const int buf = s % NBUF;
        if (s + 2 < NSTG) { CP_WAIT1(); } else { CP_WAIT0(); }
        __syncthreads();
        if (s + 2 < NSTG) issue_stage((s + 2) * KC, (s + 2) % NBUF);

        const uint32_t ab = us + (uint32_t)(buf * STGSZ) * 2;
        const uint32_t bb = us + (uint32_t)(buf * STGSZ + ASZ) * 2;
#pragma unroll
        for (int ks = 0; ks < 4; ks++) {
            const int k0 = ks * 16;
            uint32_t af[4][4], bf[4][2];
#pragma unroll
            for (int mi = 0; mi < 4; mi++)
                ldsm4(af[mi], ab + (uint32_t)((wm + mi * 16 + lrA) * LDA + k0 + lcA) * 2);
#pragma unroll
            for (int ntp = 0; ntp < 2; ntp++) {
                uint32_t kb[4];
                ldsm4t(kb, bb + (uint32_t)((k0 + lrB) * LDB + wn + ntp * 16 + lcB) * 2);
                bf[2 * ntp][0] = kb[0]; bf[2 * ntp][1] = kb[1];
                bf[2 * ntp + 1][0] = kb[2]; bf[2 * ntp + 1][1] = kb[3];
            }
#pragma unroll
            for (int mi = 0; mi < 4; mi++)
#pragma unroll
                for (int ni = 0; ni < 4; ni++)
                    mma16(acc[mi][ni], af[mi], bf[ni]);
        }
    }

    // epilogue: +bias, *oscale, fp16-round, store
#pragma unroll
    for (int mi = 0; mi < 4; mi++) {
        int r0 = bm + wm + mi * 16 + g;
#pragma unroll
        for (int ni = 0; ni < 4; ni++) {
            int col = bn + wn + ni * 8 + c * 2;
            float b0 = BIAS ? bias[col] : 0.f;
            float b1 = BIAS ? bias[col + 1] : 0.f;
            *(__half2*)&C[(size_t)r0 * D_MODEL + col] =
                __floats2half2_rn((acc[mi][ni][0] + b0) * oscale,
                                  (acc[mi][ni][1] + b1) * oscale);
            *(__half2*)&C[(size_t)(r0 + 8) * D_MODEL + col] =
                __floats2half2_rn((acc[mi][ni][2] + b0) * oscale,
                                  (acc[mi][ni][3] + b1) * oscale);
        }
    }
}

__global__ void __launch_bounds__(256, 2)
fuse_weights_mma()
{
    int z = blockIdx.z;
    gemm_cp<false>(g_Wh[z], g_Wh[3 + z], nullptr, g_Weffh[z], (z == 0) ? QSC : 1.f);
}

__global__ void __launch_bounds__(256, 2)
proj_mma()
{
    int z = blockIdx.z;
    const __half* A = (z == 0) ? g_xh : g_yh;
    gemm_cp<true>(A, g_Weffh[z], g_beff[z], g_QKVh[z], 1.f);
}

// =====================================================================
// fused bias — 8-way k-sliced (f32, reads original weights)
// =====================================================================
__global__ void fuse_bias_kernel(const float* __restrict__ bq, const float* __restrict__ bk,
                                 const float* __restrict__ bv, const float* __restrict__ Wqm,
                                 const float* __restrict__ Wkm, const float* __restrict__ Wvm,
                                 const float* __restrict__ bqm, const float* __restrict__ bkm,
                                 const float* __restrict__ bvm)
{
    __shared__ float red[8][32];
    int z = blockIdx.y;
    int t = threadIdx.x;
    int n = blockIdx.x * 32 + (t & 31);
    int ks = t >> 5;
    const float* b1 = (z == 0) ? bq  : (z == 1) ? bk  : bv;
    const float* W  = (z == 0) ? Wqm : (z == 1) ? Wkm : Wvm;
    const float* b2 = (z == 0) ? bqm : (z == 1) ? bkm : bvm;
    float s = 0.f;
    for (int k = ks * 128; k < ks * 128 + 128; k++)
        s += b1[k] * W[(size_t)k * D_MODEL + n];
    red[ks][t & 31] = s;
    __syncthreads();
    if (t < 32) {
        float acc = b2[n];
#pragma unroll
        for (int r = 0; r < 8; r++) acc += red[r][t];
        if (z == 0) acc *= QSC;
        g_beff[z][n] = acc;
    }
}

// =====================================================================
// fp16 mma flash attention v7:
//  - KV tiles of 128 rows (two 64-row halves per sync region)
//  - fp16 cp.async staging, ldmatrix fragments, Q frags register-resident
//  - P in registers; l via ones-column mma; double-buffered KV
// =====================================================================
#define LDQH 72
#define LDKH 72
#define LDVH 72
#define KVR  128
#define KVSZH (KVR*LDKH + KVR*LDVH)            // halfs per buffer
#define ATT_SMEM ((128*LDQH + 2*KVSZH) * 2)    // 92160 B

__global__ void __launch_bounds__(256, 2)
attn_mma(float* __restrict__ out)
{
    extern __shared__ __half smah[];
    const uint32_t usQ  = smem_u32(smah);
    const uint32_t usKV = usQ + 128 * LDQH * 2;

    const int tid = threadIdx.x;
    const int wid = tid >> 5, lane = tid & 31;
    const int g = lane >> 2, c = lane & 3;
    const int b = blockIdx.z, h = blockIdx.y;
    const int q0 = blockIdx.x * 128;
    const int wr = wid * 16;

    const __half* __restrict__ Qg = g_QKVh[0];
    const __half* __restrict__ Kg = g_QKVh[1];
    const __half* __restrict__ Vg = g_QKVh[2];
    const size_t basebh = (size_t)b * SEQ * D_MODEL + (size_t)h * KD;

    auto issue_kv = [&](int kv0, int bufi) {
        uint32_t dk = usKV + (uint32_t)(bufi * KVSZH) * 2;
        uint32_t dv = dk + (uint32_t)(KVR * LDKH) * 2;
#pragma unroll
        for (int q = 0; q < 4; q++) {
            int ch = q * 256 + tid;
            int row = ch >> 3, off = (ch & 7) * 8;     // 8 halfs = 16B
            const __half* gk = Kg + basebh + (size_t)(kv0 + row) * D_MODEL + off;
            CP16(dk + (uint32_t)(row * LDKH + off) * 2, gk);
            const __half* gv = Vg + basebh + (size_t)(kv0 + row) * D_MODEL + off;
            CP16(dv + (uint32_t)(row * LDVH + off) * 2, gv);
        }
        CP_COMMIT();
    };

    {   // prologue: Q tile + KV tile 0 in one group
#pragma unroll
        for (int q = 0; q < 4; q++) {
            int ch = q * 256 + tid;
            int row = ch >> 3, off = (ch & 7) * 8;
            const __half* gq = Qg + basebh + (size_t)(q0 + row) * D_MODEL + off;
            CP16(usQ + (uint32_t)(row * LDQH + off) * 2, gq);
        }
        issue_kv(0, 0);
    }

    const int lr = ((lane >> 3) & 1) * 8 + (lane & 7);
    const int lc = ((lane >> 4) & 1) * 8;
    const int lrK = ((lane >> 4) & 1) * 8 + (lane & 7);
    const int lcK = ((lane >> 3) & 1) * 8;

    uint32_t qf[4][4];
    float oacc[8][4];
#pragma unroll
    for (int i = 0; i < 8; i++)
#pragma unroll
        for (int j = 0; j < 4; j++) oacc[i][j] = 0.f;
    float lacc[4] = {0.f, 0.f, 0.f, 0.f};
    const uint32_t ones2[2] = { 0x3C003C00u, 0x3C003C00u };

    for (int it = 0; it < SEQ / KVR; it++) {
        CP_WAIT0();
        __syncthreads();
        if (it + 1 < SEQ / KVR) issue_kv((it + 1) * KVR, (it + 1) & 1);
        if (it == 0) {
#pragma unroll
            for (int kp = 0; kp < 4; kp++)
                ldsm4(qf[kp], usQ + (uint32_t)((wr + lr) * LDQH + kp * 16 + lc) * 2);
        }

        const uint32_t kb_base = usKV + (uint32_t)((it & 1) * KVSZH) * 2;
        const uint32_t vb_base = kb_base + (uint32_t)(KVR * LDKH) * 2;

#pragma unroll
        for (int half = 0; half < 2; half++) {
            const int r0 = half * 64;

            // ---- S = Q @ K^T ----
            float sacc[8][4];
#pragma unroll
            for (int i = 0; i < 8; i++)
#pragma unroll
                for (int j = 0; j < 4; j++) sacc[i][j] = 0.f;
#pragma unroll
            for (int kp = 0; kp < 4; kp++) {
#pragma unroll
                for (int ntp = 0; ntp < 4; ntp++) {
                    uint32_t kb[4];
                    ldsm4(kb, kb_base + (uint32_t)((r0 + ntp * 16 + lrK) * LDKH + kp * 16 + lcK) * 2);
                    uint32_t b0[2] = { kb[0], kb[1] };
                    uint32_t b1[2] = { kb[2], kb[3] };
                    mma16(sacc[2 * ntp], qf[kp], b0);
                    mma16(sacc[2 * ntp + 1], qf[kp], b1);
                }
            }

            // ---- p = 2^s ; pack C-frag -> A-frag ----
            uint32_t pa[4][4];
#pragma unroll
            for (int j = 0; j < 4; j++) {
                float e0 = ex2f(sacc[2 * j][0]),     e1 = ex2f(sacc[2 * j][1]);
                float e2 = ex2f(sacc[2 * j][2]),     e3 = ex2f(sacc[2 * j][3]);
                float f0 = ex2f(sacc[2 * j + 1][0]), f1 = ex2f(sacc[2 * j + 1][1]);
                float f2 = ex2f(sacc[2 * j + 1][2]), f3 = ex2f(sacc[2 * j + 1][3]);
                pa[j][0] = packh2(e1, e0);
                pa[j][1] = packh2(e3, e2);
                pa[j][2] = packh2(f1, f0);
                pa[j][3] = packh2(f3, f2);
            }

            // ---- O += P @ V ; l += P @ 1 ----
#pragma unroll
            for (int j = 0; j < 4; j++) {
#pragma unroll
                for (int dtp = 0; dtp < 4; dtp++) {
                    uint32_t vb[4];
                    ldsm4t(vb, vb_base + (uint32_t)((r0 + j * 16 + lr) * LDVH + dtp * 16 + lc) * 2);
                    uint32_t b0[2] = { vb[0], vb[1] };
                    uint32_t b1[2] = { vb[2], vb[3] };
                    mma16(oacc[2 * dtp], pa[j], b0);
                    mma16(oacc[2 * dtp + 1], pa[j], b1);
                }
                mma16(lacc, pa[j], ones2);
            }
        }
    }

    float inv0 = 1.f / lacc[0], inv1 = 1.f / lacc[2];

#pragma unroll
    for (int dt = 0; dt < 8; dt++) {
        int col = dt * 8 + 2 * c;
        *(float2*)&out[basebh + (size_t)(q0 + wr + g) * D_MODEL + col] =
            make_float2(oacc[dt][0] * inv0, oacc[dt][1] * inv0);
        *(float2*)&out[basebh + (size_t)(q0 + wr + g + 8) * D_MODEL + col] =
            make_float2(oacc[dt][2] * inv1, oacc[dt][3] * inv1);
    }
}

// =====================================================================
// Host launcher
// =====================================================================
extern "C" void kernel_launch(void* const* d_in, const int* in_sizes, int n_in,
                              void* d_out, int out_size)
{
    const float* x   = (const float*)d_in[0];
    const float* y   = (const float*)d_in[1];
    const float* Wq  = (const float*)d_in[2];
    const float* bq  = (const float*)d_in[3];
    const float* Wk  = (const float*)d_in[4];
    const float* bk  = (const float*)d_in[5];
    const float* Wv  = (const float*)d_in[6];
    const float* bv  = (const float*)d_in[7];
    const float* Wqm = (const float*)d_in[8];
    const float* bqm = (const float*)d_in[9];
    const float* Wkm = (const float*)d_in[10];
    const float* bkm = (const float*)d_in[11];
    const float* Wvm = (const float*)d_in[12];
    const float* bvm = (const float*)d_in[13];
    float* out = (float*)d_out;

    cudaFuncSetAttribute(fuse_weights_mma, cudaFuncAttributeMaxDynamicSharedMemorySize, GEMM_SMEM);
    cudaFuncSetAttribute(proj_mma, cudaFuncAttributeMaxDynamicSharedMemorySize, GEMM_SMEM);
    cudaFuncSetAttribute(attn_mma, cudaFuncAttributeMaxDynamicSharedMemorySize, ATT_SMEM);

    preround<<<dim3(4096, 8), 256>>>(x, y, Wq, Wk, Wv, Wqm, Wkm, Wvm);
    fuse_weights_mma<<<dim3(8, 8, 3), 256, GEMM_SMEM>>>();
    fuse_bias_kernel<<<dim3(32, 3), 256>>>(bq, bk, bv, Wqm, Wkm, Wvm, bqm, bkm, bvm);
    proj_mma<<<dim3(8, 32, 3), 256, GEMM_SMEM>>>();
    attn_mma<<<dim3(SEQ / 128, HEADS, BATCH), 256, ATT_SMEM>>>(out);
}

// round 15
// speedup vs baseline: 1.0791x; 1.0791x over previous
#include <cuda_runtime.h>
#include <cuda_fp16.h>
#include <math_constants.h>
#include <cstdint>

#define D_MODEL 1024
#define SEQ     2048
#define BATCH   2
#define HEADS   16
#define KD      64
#define MROWS   (BATCH*SEQ)   // 4096

// ---- scratch (device globals) ----
__device__ __half g_Wh[6][D_MODEL*D_MODEL];    // fp16 Wq,Wk,Wv,Wqm,Wkm,Wvm
__device__ __half g_xh[MROWS*D_MODEL];
__device__ __half g_yh[MROWS*D_MODEL];
__device__ __half g_Weffh[3][D_MODEL*D_MODEL]; // fp16 fused weights (z=0 *QSC)
__device__ float  g_beff[3][D_MODEL];
__device__ __half g_QKVh[3][MROWS*D_MODEL];    // fp16 Q(,*QSC)/K/V

#define QSC 0.18033688011112042f               // 0.125 * log2(e)

// =====================================================================
// helpers
// =====================================================================
__device__ __forceinline__ float ex2f(float x) {
    float r;
    asm("ex2.approx.ftz.f32 %0, %1;" : "=f"(r) : "f"(x));
    return r;
}
__device__ __forceinline__ uint32_t smem_u32(const void* p) {
    uint32_t a;
    asm("{ .reg .u64 t; cvta.to.shared.u64 t, %1; cvt.u32.u64 %0, t; }" : "=r"(a) : "l"(p));
    return a;
}
__device__ __forceinline__ uint32_t packh2(float hi, float lo) {
    uint32_t r;
    asm("cvt.rn.f16x2.f32 %0, %1, %2;" : "=r"(r) : "f"(hi), "f"(lo));
    return r;
}
__device__ __forceinline__ void mma16(float* d, const uint32_t* a, const uint32_t* b) {
    asm volatile(
        "mma.sync.aligned.m16n8k16.row.col.f32.f16.f16.f32 "
        "{%0,%1,%2,%3}, {%4,%5,%6,%7}, {%8,%9}, {%0,%1,%2,%3};"
        : "+f"(d[0]), "+f"(d[1]), "+f"(d[2]), "+f"(d[3])
        : "r"(a[0]), "r"(a[1]), "r"(a[2]), "r"(a[3]), "r"(b[0]), "r"(b[1]));
}
__device__ __forceinline__ void ldsm4(uint32_t* r, uint32_t baddr) {
    asm volatile("ldmatrix.sync.aligned.m8n8.x4.shared.b16 {%0,%1,%2,%3}, [%4];"
        : "=r"(r[0]), "=r"(r[1]), "=r"(r[2]), "=r"(r[3]) : "r"(baddr));
}
__device__ __forceinline__ void ldsm4t(uint32_t* r, uint32_t baddr) {
    asm volatile("ldmatrix.sync.aligned.m8n8.x4.trans.shared.b16 {%0,%1,%2,%3}, [%4];"
        : "=r"(r[0]), "=r"(r[1]), "=r"(r[2]), "=r"(r[3]) : "r"(baddr));
}
#define CP16(smaddr, gptr) \
    asm volatile("cp.async.cg.shared.global [%0], [%1], 16;" :: "r"(smaddr), "l"(gptr) : "memory")
#define CP_COMMIT() asm volatile("cp.async.commit_group;" ::: "memory")
#define CP_WAIT0()  asm volatile("cp.async.wait_group 0;" ::: "memory")
#define CP_WAIT1()  asm volatile("cp.async.wait_group 1;" ::: "memory")
#define CP_WAIT2()  asm volatile("cp.async.wait_group 2;" ::: "memory")

// =====================================================================
// pre-round pass: f32 -> fp16 (RNE) for x, y, 6 weights
// =====================================================================
__global__ void preround(const float* __restrict__ x, const float* __restrict__ y,
                         const float* __restrict__ Wq, const float* __restrict__ Wk,
                         const float* __restrict__ Wv, const float* __restrict__ Wqm,
                         const float* __restrict__ Wkm, const float* __restrict__ Wvm)
{
    int z = blockIdx.y;
    const float* src;
    __half* dst;
    int nf4;
    if (z == 0)      { src = x; dst = g_xh; nf4 = MROWS * D_MODEL / 4; }
    else if (z == 1) { src = y; dst = g_yh; nf4 = MROWS * D_MODEL / 4; }
    else {
        const float* ws[6] = { Wq, Wk, Wv, Wqm, Wkm, Wvm };
        src = ws[z - 2]; dst = g_Wh[z - 2]; nf4 = D_MODEL * D_MODEL / 4;
    }
    int i = blockIdx.x * 256 + threadIdx.x;
    if (i >= nf4) return;
    float4 v = ((const float4*)src)[i];
    __half2* d2 = (__half2*)dst;
    d2[2 * i]     = __floats2half2_rn(v.x, v.y);
    d2[2 * i + 1] = __floats2half2_rn(v.z, v.w);
}

// =====================================================================
// fp16 mma.sync GEMM: 128x128 CTA tile, 8 warps (2x4 -> 64x32 warp tile),
// K chunks of 32 (R13-proven), 4-stage cp.async ring with 3 in flight.
// LDA=40 / LDB=136 (fp16 units): ldmatrix rows hit distinct banks.
// =====================================================================
#define KC      32
#define NSTG    (D_MODEL / KC)     // 32
#define NBUF    4
#define LDA     40
#define LDB     136
#define ASZ     (128 * LDA)        // 5120 halfs
#define BSZ     (KC * LDB)         // 4352 halfs
#define STGSZ   (ASZ + BSZ)        // 9472 halfs
#define GEMM_SMEM (NBUF * STGSZ * 2)   // 75776 B

template<bool BIAS>
__device__ void gemm_cp(const __half* __restrict__ A, const __half* __restrict__ B,
                        const float* __restrict__ bias, __half* __restrict__ C,
                        float oscale)
{
    extern __shared__ __half smh[];
    const uint32_t us = smem_u32(smh);

    const int tid = threadIdx.x;
    const int wid = tid >> 5, lane = tid & 31;
    const int g = lane >> 2, c = lane & 3;
    const int wm = (wid & 1) * 64, wn = (wid >> 1) * 32;
    const int bm = blockIdx.y * 128, bn = blockIdx.x * 128;

    auto issue_stage = [&](int kc, int buf) {
        // A: 128 rows x 64B (4 chunks/row); 256 threads x 2 chunks
        int arow = tid >> 1;
        uint32_t da = us + (uint32_t)(buf * STGSZ + arow * LDA) * 2 + (tid & 1) * 32;
        const __half* ga = A + (size_t)(bm + arow) * D_MODEL + kc + (tid & 1) * 16;
        CP16(da, ga);
        CP16(da + 16, ga + 8);
        // B: 32 rows x 256B (16 chunks/row); 256 threads x 2 chunks
        int brow = tid >> 3;
        uint32_t db = us + (uint32_t)(buf * STGSZ + ASZ + brow * LDB) * 2 + (tid & 7) * 16;
        const __half* gb = B + (size_t)(kc + brow) * D_MODEL + bn + (tid & 7) * 8;
        CP16(db, gb);
        CP16(db + 128, gb + 64);
        CP_COMMIT();
    };

    issue_stage(0, 0);
    issue_stage(KC, 1);
    issue_stage(2 * KC, 2);

    float acc[4][4][4] = {};

    const int lrA = ((lane >> 3) & 1) * 8 + (lane & 7);
    const int lcA = ((lane >> 4) & 1) * 8;
    const int lrB = ((lane >> 3) & 1) * 8 + (lane & 7);
    const int lcB = ((lane >> 4) & 1) * 8;

    for (int s = 0; s < NSTG; s++) {
        const int buf = s % NBUF;
        if (s <= NSTG - 3)      { CP_WAIT2(); }
        else if (s == NSTG - 2) { CP_WAIT1(); }
        else                    { CP_WAIT0(); }
        __syncthreads();
        if (s + 3 < NSTG) issue_stage((s + 3) * KC, (s + 3) % NBUF);

        const uint32_t ab = us + (uint32_t)(buf * STGSZ) * 2;
        const uint32_t bb = us + (uint32_t)(buf * STGSZ + ASZ) * 2;
#pragma unroll
        for (int ks = 0; ks < 2; ks++) {
            const int k0 = ks * 16;
            uint32_t af[4][4], bf[4][2];
#pragma unroll
            for (int mi = 0; mi < 4; mi++)
                ldsm4(af[mi], ab + (uint32_t)((wm + mi * 16 + lrA) * LDA + k0 + lcA) * 2);
#pragma unroll
            for (int ntp = 0; ntp < 2; ntp++) {
                uint32_t kb[4];
                ldsm4t(kb, bb + (uint32_t)((k0 + lrB) * LDB + wn + ntp * 16 + lcB) * 2);
                bf[2 * ntp][0] = kb[0]; bf[2 * ntp][1] = kb[1];
                bf[2 * ntp + 1][0] = kb[2]; bf[2 * ntp + 1][1] = kb[3];
            }
#pragma unroll
            for (int mi = 0; mi < 4; mi++)
#pragma unroll
                for (int ni = 0; ni < 4; ni++)
                    mma16(acc[mi][ni], af[mi], bf[ni]);
        }
    }

    // epilogue: +bias, *oscale, fp16-round, store
#pragma unroll
    for (int mi = 0; mi < 4; mi++) {
        int r0 = bm + wm + mi * 16 + g;
#pragma unroll
        for (int ni = 0; ni < 4; ni++) {
            int col = bn + wn + ni * 8 + c * 2;
            float b0 = BIAS ? bias[col] : 0.f;
            float b1 = BIAS ? bias[col + 1] : 0.f;
            *(__half2*)&C[(size_t)r0 * D_MODEL + col] =
                __floats2half2_rn((acc[mi][ni][0] + b0) * oscale,
                                  (acc[mi][ni][1] + b1) * oscale);
            *(__half2*)&C[(size_t)(r0 + 8) * D_MODEL + col] =
                __floats2half2_rn((acc[mi][ni][2] + b0) * oscale,
                                  (acc[mi][ni][3] + b1) * oscale);
        }
    }
}

__global__ void __launch_bounds__(256, 2)
fuse_weights_mma()
{
    int z = blockIdx.z;
    gemm_cp<false>(g_Wh[z], g_Wh[3 + z], nullptr, g_Weffh[z], (z == 0) ? QSC : 1.f);
}

__global__ void __launch_bounds__(256, 2)
proj_mma()
{
    int z = blockIdx.z;
    const __half* A = (z == 0) ? g_xh : g_yh;
    gemm_cp<true>(A, g_Weffh[z], g_beff[z], g_QKVh[z], 1.f);
}

// =====================================================================
// fused bias — 8-way k-sliced (f32, reads original weights)
// =====================================================================
__global__ void fuse_bias_kernel(const float* __restrict__ bq, const float* __restrict__ bk,
                                 const float* __restrict__ bv, const float* __restrict__ Wqm,
                                 const float* __restrict__ Wkm, const float* __restrict__ Wvm,
                                 const float* __restrict__ bqm, const float* __restrict__ bkm,
                                 const float* __restrict__ bvm)
{
    __shared__ float red[8][32];
    int z = blockIdx.y;
    int t = threadIdx.x;
    int n = blockIdx.x * 32 + (t & 31);
    int ks = t >> 5;
    const float* b1 = (z == 0) ? bq  : (z == 1) ? bk  : bv;
    const float* W  = (z == 0) ? Wqm : (z == 1) ? Wkm : Wvm;
    const float* b2 = (z == 0) ? bqm : (z == 1) ? bkm : bvm;
    float s = 0.f;
    for (int k = ks * 128; k < ks * 128 + 128; k++)
        s += b1[k] * W[(size_t)k * D_MODEL + n];
    red[ks][t & 31] = s;
    __syncthreads();
    if (t < 32) {
        float acc = b2[n];
#pragma unroll
        for (int r = 0; r < 8; r++) acc += red[r][t];
        if (z == 0) acc *= QSC;
        g_beff[z][n] = acc;
    }
}

// =====================================================================
// fp16 mma flash attention v8 (R13 body + 3-buffer KV ring, 2 in flight):
//  - fp16 operands staged raw via cp.async, fragments via ldmatrix
//  - Q fragments hoisted into registers (loaded once)
//  - P in registers (C-frag -> A-frag via cvt.rn.f16x2)
//  - l via ones-column mma
// =====================================================================
#define LDQH 72
#define LDKH 72
#define LDVH 72
#define KVBUF 3
#define KVSZH (64*LDKH + 64*LDVH)                  // halfs per buffer
#define ATT_SMEM ((128*LDQH + KVBUF*KVSZH) * 2)    // 73728 B
#define NT (SEQ / 64)                              // 32 kv tiles

__global__ void __launch_bounds__(256, 2)
attn_mma(float* __restrict__ out)
{
    extern __shared__ __half smah[];
    const uint32_t usQ  = smem_u32(smah);
    const uint32_t usKV = usQ + 128 * LDQH * 2;

    const int tid = threadIdx.x;
    const int wid = tid >> 5, lane = tid & 31;
    const int g = lane >> 2, c = lane & 3;
    const int b = blockIdx.z, h = blockIdx.y;
    const int q0 = blockIdx.x * 128;
    const int wr = wid * 16;

    const __half* __restrict__ Qg = g_QKVh[0];
    const __half* __restrict__ Kg = g_QKVh[1];
    const __half* __restrict__ Vg = g_QKVh[2];
    const size_t basebh = (size_t)b * SEQ * D_MODEL + (size_t)h * KD;

    auto issue_kv = [&](int kv0, int bufi) {
        uint32_t dk = usKV + (uint32_t)(bufi * KVSZH) * 2;
        uint32_t dv = dk + (uint32_t)(64 * LDKH) * 2;
#pragma unroll
        for (int q = 0; q < 2; q++) {
            int ch = q * 256 + tid;
            int row = ch >> 3, off = (ch & 7) * 8;     // 8 halfs = 16B
            const __half* gk = Kg + basebh + (size_t)(kv0 + row) * D_MODEL + off;
            CP16(dk + (uint32_t)(row * LDKH + off) * 2, gk);
            const __half* gv = Vg + basebh + (size_t)(kv0 + row) * D_MODEL + off;
            CP16(dv + (uint32_t)(row * LDVH + off) * 2, gv);
        }
        CP_COMMIT();
    };

    {   // prologue: Q tile + KV tile 0 in one group, KV tile 1 in a second
#pragma unroll
        for (int q = 0; q < 4; q++) {
            int ch = q * 256 + tid;
            int row = ch >> 3, off = (ch & 7) * 8;
            const __half* gq = Qg + basebh + (size_t)(q0 + row) * D_MODEL + off;
            CP16(usQ + (uint32_t)(row * LDQH + off) * 2, gq);
        }
        issue_kv(0, 0);
        issue_kv(64, 1);
    }

    const int lr = ((lane >> 3) & 1) * 8 + (lane & 7);
    const int lc = ((lane >> 4) & 1) * 8;
    const int lrK = ((lane >> 4) & 1) * 8 + (lane & 7);  // K non-trans: n split on bit4
    const int lcK = ((lane >> 3) & 1) * 8;

    uint32_t qf[4][4];
    float oacc[8][4];
#pragma unroll
    for (int i = 0; i < 8; i++)
#pragma unroll
        for (int j = 0; j < 4; j++) oacc[i][j] = 0.f;
    float lacc[4] = {0.f, 0.f, 0.f, 0.f};
    const uint32_t ones2[2] = { 0x3C003C00u, 0x3C003C00u };

    for (int it = 0; it < NT; it++) {
        if (it <= NT - 2) { CP_WAIT1(); } else { CP_WAIT0(); }
        __syncthreads();
        if (it + 2 < NT) issue_kv((it + 2) * 64, (it + 2) % KVBUF);
        if (it == 0) {
#pragma unroll
            for (int kp = 0; kp < 4; kp++)
                ldsm4(qf[kp], usQ + (uint32_t)((wr + lr) * LDQH + kp * 16 + lc) * 2);
        }

        const uint32_t kb_base = usKV + (uint32_t)((it % KVBUF) * KVSZH) * 2;
        const uint32_t vb_base = kb_base + (uint32_t)(64 * LDKH) * 2;

        // ---- S = Q @ K^T ----
        float sacc[8][4];
#pragma unroll
        for (int i = 0; i < 8; i++)
#pragma unroll
            for (int j = 0; j < 4; j++) sacc[i][j] = 0.f;
#pragma unroll
        for (int kp = 0; kp < 4; kp++) {
#pragma unroll
            for (int ntp = 0; ntp < 4; ntp++) {
                uint32_t kb[4];
                ldsm4(kb, kb_base + (uint32_t)((ntp * 16 + lrK) * LDKH + kp * 16 + lcK) * 2);
                uint32_t b0[2] = { kb[0], kb[1] };
                uint32_t b1[2] = { kb[2], kb[3] };
                mma16(sacc[2 * ntp], qf[kp], b0);
                mma16(sacc[2 * ntp + 1], qf[kp], b1);
            }
        }

        // ---- p = 2^s ; pack C-frag -> A-frag (fp16x2) ----
        uint32_t pa[4][4];
#pragma unroll
        for (int j = 0; j < 4; j++) {
            float e0 = ex2f(sacc[2 * j][0]),     e1 = ex2f(sacc[2 * j][1]);
            float e2 = ex2f(sacc[2 * j][2]),     e3 = ex2f(sacc[2 * j][3]);
            float f0 = ex2f(sacc[2 * j + 1][0]), f1 = ex2f(sacc[2 * j + 1][1]);
            float f2 = ex2f(sacc[2 * j + 1][2]), f3 = ex2f(sacc[2 * j + 1][3]);
            pa[j][0] = packh2(e1, e0);
            pa[j][1] = packh2(e3, e2);
            pa[j][2] = packh2(f1, f0);
            pa[j][3] = packh2(f3, f2);
        }

        // ---- O += P @ V ; l += P @ 1 ----
#pragma unroll
        for (int j = 0; j < 4; j++) {
#pragma unroll
            for (int dtp = 0; dtp < 4; dtp++) {
                uint32_t vb[4];
                ldsm4t(vb, vb_base + (uint32_t)((j * 16 + lr) * LDVH + dtp * 16 + lc) * 2);
                uint32_t b0[2] = { vb[0], vb[1] };
                uint32_t b1[2] = { vb[2], vb[3] };
                mma16(oacc[2 * dtp], pa[j], b0);
                mma16(oacc[2 * dtp + 1], pa[j], b1);
            }
            mma16(lacc, pa[j], ones2);
        }
    }

    float inv0 = 1.f / lacc[0], inv1 = 1.f / lacc[2];

#pragma unroll
    for (int dt = 0; dt < 8; dt++) {
        int col = dt * 8 + 2 * c;
        *(float2*)&out[basebh + (size_t)(q0 + wr + g) * D_MODEL + col] =
            make_float2(oacc[dt][0] * inv0, oacc[dt][1] * inv0);
        *(float2*)&out[basebh + (size_t)(q0 + wr + g + 8) * D_MODEL + col] =
            make_float2(oacc[dt][2] * inv1, oacc[dt][3] * inv1);
    }
}

// =====================================================================
// Host launcher
// =====================================================================
extern "C" void kernel_launch(void* const* d_in, const int* in_sizes, int n_in,
                              void* d_out, int out_size)
{
    const float* x   = (const float*)d_in[0];
    const float* y   = (const float*)d_in[1];
    const float* Wq  = (const float*)d_in[2];
    const float* bq  = (const float*)d_in[3];
    const float* Wk  = (const float*)d_in[4];
    const float* bk  = (const float*)d_in[5];
    const float* Wv  = (const float*)d_in[6];
    const float* bv  = (const float*)d_in[7];
    const float* Wqm = (const float*)d_in[8];
    const float* bqm = (const float*)d_in[9];
    const float* Wkm = (const float*)d_in[10];
    const float* bkm = (const float*)d_in[11];
    const float* Wvm = (const float*)d_in[12];
    const float* bvm = (const float*)d_in[13];
    float* out = (float*)d_out;

    cudaFuncSetAttribute(fuse_weights_mma, cudaFuncAttributeMaxDynamicSharedMemorySize, GEMM_SMEM);
    cudaFuncSetAttribute(proj_mma, cudaFuncAttributeMaxDynamicSharedMemorySize, GEMM_SMEM);
    cudaFuncSetAttribute(attn_mma, cudaFuncAttributeMaxDynamicSharedMemorySize, ATT_SMEM);

    preround<<<dim3(4096, 8), 256>>>(x, y, Wq, Wk, Wv, Wqm, Wkm, Wvm);
    fuse_weights_mma<<<dim3(8, 8, 3), 256, GEMM_SMEM>>>();
    fuse_bias_kernel<<<dim3(32, 3), 256>>>(bq, bk, bv, Wqm, Wkm, Wvm, bqm, bkm, bvm);
    proj_mma<<<dim3(8, 32, 3), 256, GEMM_SMEM>>>();
    attn_mma<<<dim3(SEQ / 128, HEADS, BATCH), 256, ATT_SMEM>>>(out);
}

// round 16
// speedup vs baseline: 1.1349x; 1.0517x over previous
#include <cuda_runtime.h>
#include <cuda_fp16.h>
#include <math_constants.h>
#include <cstdint>

#define D_MODEL 1024
#define SEQ     2048
#define BATCH   2
#define HEADS   16
#define KD      64
#define MROWS   (BATCH*SEQ)   // 4096

// ---- scratch (device globals) ----
__device__ __half g_Wh[6][D_MODEL*D_MODEL];    // fp16 Wq,Wk,Wv,Wqm,Wkm,Wvm
__device__ __half g_xh[MROWS*D_MODEL];
__device__ __half g_yh[MROWS*D_MODEL];
__device__ __half g_Weffh[3][D_MODEL*D_MODEL]; // fp16 fused weights (z=0 *QSC)
__device__ float  g_beff[3][D_MODEL];
__device__ __half g_QKVh[3][MROWS*D_MODEL];    // fp16 Q(,*QSC)/K/V

#define QSC 0.18033688011112042f               // 0.125 * log2(e)

// =====================================================================
// helpers
// =====================================================================
__device__ __forceinline__ float ex2f(float x) {
    float r;
    asm("ex2.approx.ftz.f32 %0, %1;" : "=f"(r) : "f"(x));
    return r;
}
__device__ __forceinline__ uint32_t smem_u32(const void* p) {
    uint32_t a;
    asm("{ .reg .u64 t; cvta.to.shared.u64 t, %1; cvt.u32.u64 %0, t; }" : "=r"(a) : "l"(p));
    return a;
}
__device__ __forceinline__ uint32_t packh2(float hi, float lo) {
    uint32_t r;
    asm("cvt.rn.f16x2.f32 %0, %1, %2;" : "=r"(r) : "f"(hi), "f"(lo));
    return r;
}
__device__ __forceinline__ void mma16(float* d, const uint32_t* a, const uint32_t* b) {
    asm volatile(
        "mma.sync.aligned.m16n8k16.row.col.f32.f16.f16.f32 "
        "{%0,%1,%2,%3}, {%4,%5,%6,%7}, {%8,%9}, {%0,%1,%2,%3};"
        : "+f"(d[0]), "+f"(d[1]), "+f"(d[2]), "+f"(d[3])
        : "r"(a[0]), "r"(a[1]), "r"(a[2]), "r"(a[3]), "r"(b[0]), "r"(b[1]));
}
__device__ __forceinline__ void ldsm4(uint32_t* r, uint32_t baddr) {
    asm volatile("ldmatrix.sync.aligned.m8n8.x4.shared.b16 {%0,%1,%2,%3}, [%4];"
        : "=r"(r[0]), "=r"(r[1]), "=r"(r[2]), "=r"(r[3]) : "r"(baddr));
}
__device__ __forceinline__ void ldsm4t(uint32_t* r, uint32_t baddr) {
    asm volatile("ldmatrix.sync.aligned.m8n8.x4.trans.shared.b16 {%0,%1,%2,%3}, [%4];"
        : "=r"(r[0]), "=r"(r[1]), "=r"(r[2]), "=r"(r[3]) : "r"(baddr));
}
#define CP16(smaddr, gptr) \
    asm volatile("cp.async.cg.shared.global [%0], [%1], 16;" :: "r"(smaddr), "l"(gptr) : "memory")
#define CP_COMMIT() asm volatile("cp.async.commit_group;" ::: "memory")
#define CP_WAIT0()  asm volatile("cp.async.wait_group 0;" ::: "memory")
#define CP_WAIT1()  asm volatile("cp.async.wait_group 1;" ::: "memory")

// =====================================================================
// merged pre-pass:
//   z = 0..7 : f32 -> fp16 (RNE) rounding of x, y, 6 weights
//   z = 8    : fused bias  beff[zb] = b1 @ W2 + b2  (8-way k-sliced)
// =====================================================================
__global__ void preround_bias(const float* __restrict__ x, const float* __restrict__ y,
                              const float* __restrict__ Wq, const float* __restrict__ Wk,
                              const float* __restrict__ Wv, const float* __restrict__ Wqm,
                              const float* __restrict__ Wkm, const float* __restrict__ Wvm,
                              const float* __restrict__ bq, const float* __restrict__ bk,
                              const float* __restrict__ bv, const float* __restrict__ bqm,
                              const float* __restrict__ bkm, const float* __restrict__ bvm)
{
    int z = blockIdx.y;
    if (z == 8) {
        // ---- fused bias path: active blocks blockIdx.x < 128 with (x&3)<3 ----
        int zb = blockIdx.x & 3;
        int nb = blockIdx.x >> 2;
        if (zb == 3 || nb >= 32) return;
        __shared__ float red[8][32];
        int t = threadIdx.x;
        int n = nb * 32 + (t & 31);
        int ks = t >> 5;
        const float* b1 = (zb == 0) ? bq  : (zb == 1) ? bk  : bv;
        const float* W  = (zb == 0) ? Wqm : (zb == 1) ? Wkm : Wvm;
        const float* b2 = (zb == 0) ? bqm : (zb == 1) ? bkm : bvm;
        float s = 0.f;
        for (int k = ks * 128; k < ks * 128 + 128; k++)
            s += b1[k] * W[(size_t)k * D_MODEL + n];
        red[ks][t & 31] = s;
        __syncthreads();
        if (t < 32) {
            float acc = b2[n];
#pragma unroll
            for (int r = 0; r < 8; r++) acc += red[r][t];
            if (zb == 0) acc *= QSC;
            g_beff[zb][n] = acc;
        }
        return;
    }

    const float* src;
    __half* dst;
    int nf4;
    if (z == 0)      { src = x; dst = g_xh; nf4 = MROWS * D_MODEL / 4; }
    else if (z == 1) { src = y; dst = g_yh; nf4 = MROWS * D_MODEL / 4; }
    else {
        const float* ws[6] = { Wq, Wk, Wv, Wqm, Wkm, Wvm };
        src = ws[z - 2]; dst = g_Wh[z - 2]; nf4 = D_MODEL * D_MODEL / 4;
    }
    int i = blockIdx.x * 256 + threadIdx.x;
    if (i >= nf4) return;
    float4 v = ((const float4*)src)[i];
    __half2* d2 = (__half2*)dst;
    d2[2 * i]     = __floats2half2_rn(v.x, v.y);
    d2[2 * i + 1] = __floats2half2_rn(v.z, v.w);
}

// =====================================================================
// fp16 mma.sync GEMM (R13-proven, byte-identical): 128x128 CTA tile,
// 8 warps (2x4 -> 64x32 warp tile), KC=32, 3-stage cp.async ring.
// LDA=40 / LDB=136 (fp16 units): ldmatrix rows hit distinct banks.
// =====================================================================
#define KC      32
#define NSTG    (D_MODEL / KC)
#define NBUF    3
#define LDA     40
#define LDB     136
#define ASZ     (128 * LDA)        // 5120 halfs
#define BSZ     (KC * LDB)         // 4352 halfs
#define STGSZ   (ASZ + BSZ)        // 9472 halfs
#define GEMM_SMEM (NBUF * STGSZ * 2)   // 56832 B

template<bool BIAS>
__device__ void gemm_cp(const __half* __restrict__ A, const __half* __restrict__ B,
                        const float* __restrict__ bias, __half* __restrict__ C,
                        float oscale)
{
    extern __shared__ __half smh[];
    const uint32_t us = smem_u32(smh);

    const int tid = threadIdx.x;
    const int wid = tid >> 5, lane = tid & 31;
    const int g = lane >> 2, c = lane & 3;
    const int wm = (wid & 1) * 64, wn = (wid >> 1) * 32;
    const int bm = blockIdx.y * 128, bn = blockIdx.x * 128;

    auto issue_stage = [&](int kc, int buf) {
        int arow = tid >> 1;
        uint32_t da = us + (uint32_t)(buf * STGSZ + arow * LDA) * 2 + (tid & 1) * 32;
        const __half* ga = A + (size_t)(bm + arow) * D_MODEL + kc + (tid & 1) * 16;
        CP16(da, ga);
        CP16(da + 16, ga + 8);
        int brow = tid >> 3;
        uint32_t db = us + (uint32_t)(buf * STGSZ + ASZ + brow * LDB) * 2 + (tid & 7) * 16;
        const __half* gb = B + (size_t)(kc + brow) * D_MODEL + bn + (tid & 7) * 8;
        CP16(db, gb);
        CP16(db + 128, gb + 64);
        CP_COMMIT();
    };

    issue_stage(0, 0);
    issue_stage(KC, 1);

    float acc[4][4][4] = {};

    const int lrA = ((lane >> 3) & 1) * 8 + (lane & 7);
    const int lcA = ((lane >> 4) & 1) * 8;
    const int lrB = ((lane >> 3) & 1) * 8 + (lane & 7);
    const int lcB = ((lane >> 4) & 1) * 8;

    for (int s = 0; s < NSTG; s++) {
        const int buf = s % NBUF;
        if (s + 2 < NSTG) { CP_WAIT1(); } else { CP_WAIT0(); }
        __syncthreads();
        if (s + 2 < NSTG) issue_stage((s + 2) * KC, (s + 2) % NBUF);

        const uint32_t ab = us + (uint32_t)(buf * STGSZ) * 2;
        const uint32_t bb = us + (uint32_t)(buf * STGSZ + ASZ) * 2;
#pragma unroll
        for (int ks = 0; ks < 2; ks++) {
            const int k0 = ks * 16;
            uint32_t af[4][4], bf[4][2];
#pragma unroll
            for (int mi = 0; mi < 4; mi++)
                ldsm4(af[mi], ab + (uint32_t)((wm + mi * 16 + lrA) * LDA + k0 + lcA) * 2);
#pragma unroll
            for (int ntp = 0; ntp < 2; ntp++) {
                uint32_t kb[4];
                ldsm4t(kb, bb + (uint32_t)((k0 + lrB) * LDB + wn + ntp * 16 + lcB) * 2);
                bf[2 * ntp][0] = kb[0]; bf[2 * ntp][1] = kb[1];
                bf[2 * ntp + 1][0] = kb[2]; bf[2 * ntp + 1][1] = kb[3];
            }
#pragma unroll
            for (int mi = 0; mi < 4; mi++)
#pragma unroll
                for (int ni = 0; ni < 4; ni++)
                    mma16(acc[mi][ni], af[mi], bf[ni]);
        }
    }

    // epilogue: +bias, *oscale, fp16-round, store
#pragma unroll
    for (int mi = 0; mi < 4; mi++) {
        int r0 = bm + wm + mi * 16 + g;
#pragma unroll
        for (int ni = 0; ni < 4; ni++) {
            int col = bn + wn + ni * 8 + c * 2;
            float b0 = BIAS ? bias[col] : 0.f;
            float b1 = BIAS ? bias[col + 1] : 0.f;
            *(__half2*)&C[(size_t)r0 * D_MODEL + col] =
                __floats2half2_rn((acc[mi][ni][0] + b0) * oscale,
                                  (acc[mi][ni][1] + b1) * oscale);
            *(__half2*)&C[(size_t)(r0 + 8) * D_MODEL + col] =
                __floats2half2_rn((acc[mi][ni][2] + b0) * oscale,
                                  (acc[mi][ni][3] + b1) * oscale);
        }
    }
}

__global__ void __launch_bounds__(256, 2)
fuse_weights_mma()
{
    int z = blockIdx.z;
    gemm_cp<false>(g_Wh[z], g_Wh[3 + z], nullptr, g_Weffh[z], (z == 0) ? QSC : 1.f);
}

__global__ void __launch_bounds__(256, 2)
proj_mma()
{
    int z = blockIdx.z;
    const __half* A = (z == 0) ? g_xh : g_yh;
    gemm_cp<true>(A, g_Weffh[z], g_beff[z], g_QKVh[z], 1.f);
}

// =====================================================================
// fp16 mma flash attention v9 (R13 body, l moved OFF the tensor pipe):
//  - fp16 operands staged raw via cp.async, fragments via ldmatrix
//  - Q fragments hoisted into registers (loaded once)
//  - P in registers (C-frag -> A-frag via cvt.rn.f16x2)
//  - l accumulated in f32 on the FMA pipe (frees 4 mma/iter of tensor time)
//  - double-buffered KV; one __syncthreads per kv tile
// =====================================================================
#define LDQH 72
#define LDKH 72
#define LDVH 72
#define KVSZH (64*LDKH + 64*LDVH)              // halfs
#define ATT_SMEM ((128*LDQH + 2*KVSZH) * 2)    // 55296 B

__global__ void __launch_bounds__(256, 2)
attn_mma(float* __restrict__ out)
{
    extern __shared__ __half smah[];
    const uint32_t usQ  = smem_u32(smah);
    const uint32_t usKV = usQ + 128 * LDQH * 2;

    const int tid = threadIdx.x;
    const int wid = tid >> 5, lane = tid & 31;
    const int g = lane >> 2, c = lane & 3;
    const int b = blockIdx.z, h = blockIdx.y;
    const int q0 = blockIdx.x * 128;
    const int wr = wid * 16;

    const __half* __restrict__ Qg = g_QKVh[0];
    const __half* __restrict__ Kg = g_QKVh[1];
    const __half* __restrict__ Vg = g_QKVh[2];
    const size_t basebh = (size_t)b * SEQ * D_MODEL + (size_t)h * KD;

    auto issue_kv = [&](int kv0, int bufi) {
        uint32_t dk = usKV + (uint32_t)(bufi * KVSZH) * 2;
        uint32_t dv = dk + (uint32_t)(64 * LDKH) * 2;
#pragma unroll
        for (int q = 0; q < 2; q++) {
            int ch = q * 256 + tid;
            int row = ch >> 3, off = (ch & 7) * 8;     // 8 halfs = 16B
            const __half* gk = Kg + basebh + (size_t)(kv0 + row) * D_MODEL + off;
            CP16(dk + (uint32_t)(row * LDKH + off) * 2, gk);
            const __half* gv = Vg + basebh + (size_t)(kv0 + row) * D_MODEL + off;
            CP16(dv + (uint32_t)(row * LDVH + off) * 2, gv);
        }
        CP_COMMIT();
    };

    {   // prologue: Q tile + KV tile 0 in one group
#pragma unroll
        for (int q = 0; q < 4; q++) {
            int ch = q * 256 + tid;
            int row = ch >> 3, off = (ch & 7) * 8;
            const __half* gq = Qg + basebh + (size_t)(q0 + row) * D_MODEL + off;
            CP16(usQ + (uint32_t)(row * LDQH + off) * 2, gq);
        }
        issue_kv(0, 0);
    }

    const int lr = ((lane >> 3) & 1) * 8 + (lane & 7);
    const int lc = ((lane >> 4) & 1) * 8;
    const int lrK = ((lane >> 4) & 1) * 8 + (lane & 7);  // K non-trans: n split on bit4
    const int lcK = ((lane >> 3) & 1) * 8;

    uint32_t qf[4][4];
    float oacc[8][4];
#pragma unroll
    for (int i = 0; i < 8; i++)
#pragma unroll
        for (int j = 0; j < 4; j++) oacc[i][j] = 0.f;
    float l0 = 0.f, l1 = 0.f;

    for (int it = 0; it < SEQ / 64; it++) {
        CP_WAIT0();
        __syncthreads();
        if (it + 1 < SEQ / 64) issue_kv((it + 1) * 64, (it + 1) & 1);
        if (it == 0) {
#pragma unroll
            for (int kp = 0; kp < 4; kp++)
                ldsm4(qf[kp], usQ + (uint32_t)((wr + lr) * LDQH + kp * 16 + lc) * 2);
        }

        const uint32_t kb_base = usKV + (uint32_t)((it & 1) * KVSZH) * 2;
        const uint32_t vb_base = kb_base + (uint32_t)(64 * LDKH) * 2;

        // ---- S = Q @ K^T ----
        float sacc[8][4];
#pragma unroll
        for (int i = 0; i < 8; i++)
#pragma unroll
            for (int j = 0; j < 4; j++) sacc[i][j] = 0.f;
#pragma unroll
        for (int kp = 0; kp < 4; kp++) {
#pragma unroll
            for (int ntp = 0; ntp < 4; ntp++) {
                uint32_t kb[4];
                ldsm4(kb, kb_base + (uint32_t)((ntp * 16 + lrK) * LDKH + kp * 16 + lcK) * 2);
                uint32_t b0[2] = { kb[0], kb[1] };
                uint32_t b1[2] = { kb[2], kb[3] };
                mma16(sacc[2 * ntp], qf[kp], b0);
                mma16(sacc[2 * ntp + 1], qf[kp], b1);
            }
        }

        // ---- p = 2^s ; l += p (FMA pipe) ; pack C-frag -> A-frag ----
        uint32_t pa[4][4];
#pragma unroll
        for (int j = 0; j < 4; j++) {
            float e0 = ex2f(sacc[2 * j][0]),     e1 = ex2f(sacc[2 * j][1]);
            float e2 = ex2f(sacc[2 * j][2]),     e3 = ex2f(sacc[2 * j][3]);
            float f0 = ex2f(sacc[2 * j + 1][0]), f1 = ex2f(sacc[2 * j + 1][1]);
            float f2 = ex2f(sacc[2 * j + 1][2]), f3 = ex2f(sacc[2 * j + 1][3]);
            l0 += (e0 + e1) + (f0 + f1);   // rows g
            l1 += (e2 + e3) + (f2 + f3);   // rows g+8
            pa[j][0] = packh2(e1, e0);
            pa[j][1] = packh2(e3, e2);
            pa[j][2] = packh2(f1, f0);
            pa[j][3] = packh2(f3, f2);
        }

        // ---- O += P @ V ----
#pragma unroll
        for (int j = 0; j < 4; j++) {
#pragma unroll
            for (int dtp = 0; dtp < 4; dtp++) {
                uint32_t vb[4];
                ldsm4t(vb, vb_base + (uint32_t)((j * 16 + lr) * LDVH + dtp * 16 + lc) * 2);
                uint32_t b0[2] = { vb[0], vb[1] };
                uint32_t b1[2] = { vb[2], vb[3] };
                mma16(oacc[2 * dtp], pa[j], b0);
                mma16(oacc[2 * dtp + 1], pa[j], b1);
            }
        }
    }

    // reduce l over the 4 lanes of the quad (cols split across c)
    l0 += __shfl_xor_sync(0xffffffffu, l0, 1);
    l0 += __shfl_xor_sync(0xffffffffu, l0, 2);
    l1 += __shfl_xor_sync(0xffffffffu, l1, 1);
    l1 += __shfl_xor_sync(0xffffffffu, l1, 2);
    float inv0 = 1.f / l0, inv1 = 1.f / l1;

#pragma unroll
    for (int dt = 0; dt < 8; dt++) {
        int col = dt * 8 + 2 * c;
        *(float2*)&out[basebh + (size_t)(q0 + wr + g) * D_MODEL + col] =
            make_float2(oacc[dt][0] * inv0, oacc[dt][1] * inv0);
        *(float2*)&out[basebh + (size_t)(q0 + wr + g + 8) * D_MODEL + col] =
            make_float2(oacc[dt][2] * inv1, oacc[dt][3] * inv1);
    }
}

// =====================================================================
// Host launcher
// =====================================================================
extern "C" void kernel_launch(void* const* d_in, const int* in_sizes, int n_in,
                              void* d_out, int out_size)
{
    const float* x   = (const float*)d_in[0];
    const float* y   = (const float*)d_in[1];
    const float* Wq  = (const float*)d_in[2];
    const float* bq  = (const float*)d_in[3];
    const float* Wk  = (const float*)d_in[4];
    const float* bk  = (const float*)d_in[5];
    const float* Wv  = (const float*)d_in[6];
    const float* bv  = (const float*)d_in[7];
    const float* Wqm = (const float*)d_in[8];
    const float* bqm = (const float*)d_in[9];
    const float* Wkm = (const float*)d_in[10];
    const float* bkm = (const float*)d_in[11];
    const float* Wvm = (const float*)d_in[12];
    const float* bvm = (const float*)d_in[13];
    float* out = (float*)d_out;

    cudaFuncSetAttribute(fuse_weights_mma, cudaFuncAttributeMaxDynamicSharedMemorySize, GEMM_SMEM);
    cudaFuncSetAttribute(proj_mma, cudaFuncAttributeMaxDynamicSharedMemorySize, GEMM_SMEM);
    cudaFuncSetAttribute(attn_mma, cudaFuncAttributeMaxDynamicSharedMemorySize, ATT_SMEM);

    preround_bias<<<dim3(4096, 9), 256>>>(x, y, Wq, Wk, Wv, Wqm, Wkm, Wvm,
                                          bq, bk, bv, bqm, bkm, bvm);
    fuse_weights_mma<<<dim3(8, 8, 3), 256, GEMM_SMEM>>>();
    proj_mma<<<dim3(8, 32, 3), 256, GEMM_SMEM>>>();
    attn_mma<<<dim3(SEQ / 128, HEADS, BATCH), 256, ATT_SMEM>>>(out);
}